// round 5
// baseline (speedup 1.0000x reference)
#include <cuda_runtime.h>
#include <math.h>

#define BB 16
#define NN 131072
#define GG 16
#define BN (BB*NN)
#define BG (BB*GG)
#define CAP 16384            // per-(b,g) bucket capacity (expected ~4096, huge margin)

// ---------------- scratch (device globals; zero at load, re-zeroed by finalizer) ----------------
__device__ unsigned g_ckeys[BG * CAP];   // bucketed keys, segment bg at bg*CAP
__device__ unsigned g_bcnt[BG];          // per-(b,g) counts (start 0 each launch)
__device__ unsigned g_mg[BN / 4];        // packed (valid<<4)|group, one byte/point
__device__ float    g_inv[BG];           // 1 / clamp(|median|, eps)
__device__ double   g_psum[32];          // distributed loss partials
__device__ unsigned g_done;              // loss block completion counter

// order-preserving map f32 -> u32 (ascending)
__device__ __forceinline__ unsigned key_of(float z) {
    unsigned u = __float_as_uint(z);
    return (u & 0x80000000u) ? ~u : (u | 0x80000000u);
}

// ---------------- K1: bucketed scatter, 8 pts/thread, smem-staged coalesced writes ----------------
__global__ void k_scatter(const float* __restrict__ target, const int* __restrict__ mask,
                          const int* __restrict__ groups) {
    __shared__ unsigned s_cnt[64][16];     // slot = wid*8 + e
    __shared__ unsigned s_gstart[17];      // block-local group starts (+ total)
    __shared__ unsigned s_gbase[16];       // global base per group
    __shared__ unsigned s_keys[2048];      // staged keys grouped by bucket
    __shared__ unsigned char s_gid[2048];  // group id per staged key
    unsigned p0 = blockIdx.x * 2048u + threadIdx.x * 8u;  // 8 consecutive points/thread
    int b = blockIdx.x >> 6;               // 64 blocks per batch
    int wid = threadIdx.x >> 5, lane = threadIdx.x & 31;

#pragma unroll
    for (int j = 0; j < 4; j++)
        ((unsigned*)s_cnt)[j * 256 + threadIdx.x] = 0;

    const int4* mp = reinterpret_cast<const int4*>(mask + p0);
    const int4* gp = reinterpret_cast<const int4*>(groups + p0);
    int4 m40 = mp[0], m41 = mp[1];
    int4 g40 = gp[0], g41 = gp[1];
    const float4* tt = reinterpret_cast<const float4*>(target + 3u * p0);
    float4 t0 = tt[0], t1 = tt[1], t2 = tt[2], t3 = tt[3], t4 = tt[4], t5 = tt[5];
    int   m[8] = {m40.x, m40.y, m40.z, m40.w, m41.x, m41.y, m41.z, m41.w};
    int   g[8] = {g40.x & 15, g40.y & 15, g40.z & 15, g40.w & 15,
                  g41.x & 15, g41.y & 15, g41.z & 15, g41.w & 15};
    float z[8] = {t0.z, t1.y, t2.x, t2.w, t3.z, t4.y, t5.x, t5.w};

    unsigned mgA = 0, mgB = 0;
#pragma unroll
    for (int e = 0; e < 4; e++) {
        mgA |= ((m[e]     ? 0x10u : 0u) | (unsigned)g[e])     << (8 * e);
        mgB |= ((m[e + 4] ? 0x10u : 0u) | (unsigned)g[e + 4]) << (8 * e);
    }
    reinterpret_cast<uint2*>(g_mg)[p0 >> 3] = make_uint2(mgA, mgB);
    __syncthreads();   // s_cnt zero visible

    unsigned peers[8];
#pragma unroll
    for (int e = 0; e < 8; e++) {
        unsigned tag = m[e] ? (unsigned)g[e] : 0xFFFFFFFFu;
        peers[e] = __match_any_sync(0xffffffffu, tag);
        if (m[e] && lane == (__ffs(peers[e]) - 1))
            s_cnt[wid * 8 + e][g[e]] = __popc(peers[e]);
    }
    __syncthreads();

    if (threadIdx.x < 16) {
        unsigned run = 0;
#pragma unroll
        for (int s = 0; s < 64; s++) {
            unsigned c = s_cnt[s][threadIdx.x];
            s_cnt[s][threadIdx.x] = run;
            run += c;
        }
        unsigned incl = run;
#pragma unroll
        for (int o = 1; o < 16; o <<= 1) {
            unsigned n = __shfl_up_sync(0x0000FFFFu, incl, o);
            if (lane >= o) incl += n;
        }
        s_gstart[threadIdx.x] = incl - run;
        if (threadIdx.x == 15) s_gstart[16] = incl;
        s_gbase[threadIdx.x] = run ? atomicAdd(&g_bcnt[b * GG + threadIdx.x], run) : 0u;
    }
    __syncthreads();

#pragma unroll
    for (int e = 0; e < 8; e++) {
        if (m[e]) {
            unsigned local = s_gstart[g[e]] + s_cnt[wid * 8 + e][g[e]]
                           + __popc(peers[e] & ((1u << lane) - 1u));
            s_keys[local] = key_of(z[e]);
            s_gid[local] = (unsigned char)g[e];
        }
    }
    __syncthreads();

    unsigned total = s_gstart[16];
    for (unsigned idx = threadIdx.x; idx < total; idx += 256u) {
        unsigned key = s_keys[idx];
        int gg = s_gid[idx];
        unsigned dst = (unsigned)(b * GG + gg) * CAP + s_gbase[gg] + (idx - s_gstart[gg]);
        g_ckeys[dst] = key;   // coalesced runs per group
    }
}

// ---------------- K2: per-(b,g) lower-median, smem-resident 8-bit radix select ----------------
#define SELCAP 12288
__global__ void k_select() {
    __shared__ unsigned s_hist[256];
    __shared__ unsigned s_wsum[8];
    __shared__ unsigned s_buf[SELCAP];
    __shared__ unsigned sh_sel, sh_k;
    int bg = blockIdx.x;
    unsigned segbase = (unsigned)bg * CAP;
    unsigned cnt = g_bcnt[bg];
    if (cnt == 0) {
        if (threadIdx.x == 0) g_inv[bg] = 1.0f;
        return;
    }
    bool in_smem = (cnt <= SELCAP);
    if (in_smem)
        for (unsigned i = threadIdx.x; i < cnt; i += 512u) s_buf[i] = g_ckeys[segbase + i];
    __syncthreads();

    unsigned k = (cnt - 1u) >> 1;            // lower median index
    unsigned prefix = 0, pmask = 0;
    int t = threadIdx.x, lane = t & 31;

    for (int level = 0; level < 4; level++) {
        int shift = 24 - 8 * level;
        if (t < 256) s_hist[t] = 0;
        __syncthreads();
        for (unsigned i = t; i < ((cnt + 511u) & ~511u); i += 512u) {
            unsigned bin = 0xFFFFFFFFu;
            if (i < cnt) {
                unsigned key = in_smem ? s_buf[i] : g_ckeys[segbase + i];
                if ((key & pmask) == prefix) bin = (key >> shift) & 255u;
            }
            unsigned peers = __match_any_sync(0xffffffffu, bin);
            if (bin != 0xFFFFFFFFu && lane == (__ffs(peers) - 1))
                atomicAdd(&s_hist[bin], (unsigned)__popc(peers));
        }
        __syncthreads();
        if (t < 256) {
            unsigned v = s_hist[t];
            unsigned incl = v;
#pragma unroll
            for (int o = 1; o < 32; o <<= 1) {
                unsigned n = __shfl_up_sync(0xffffffffu, incl, o);
                if (lane >= o) incl += n;
            }
            if (lane == 31) s_wsum[t >> 5] = incl;
            __syncwarp();
            // wait for all 8 warp sums
            __syncthreads();
            unsigned off = 0;
#pragma unroll
            for (int w = 0; w < 8; w++) off += (w < (t >> 5)) ? s_wsum[w] : 0u;
            incl += off;
            unsigned excl = incl - v;
            if (k >= excl && k < incl) { sh_sel = (unsigned)t; sh_k = k - excl; }
        } else {
            __syncthreads();
        }
        __syncthreads();
        prefix |= sh_sel << shift;
        pmask  |= 255u << shift;
        k = sh_k;
        __syncthreads();
    }
    if (t == 0) {
        unsigned kk = prefix;
        unsigned ub = (kk & 0x80000000u) ? (kk & 0x7fffffffu) : ~kk;
        float med = __uint_as_float(ub);
        if (!isfinite(med)) med = 1.0f;      // nan_to_num semantics
        float ns = fmaxf(fabsf(med), 1e-6f);
        g_inv[bg] = 1.0f / ns;
    }
}

// ---------------- K3: fused loss pass + reduction + last-block finalize/reset ----------------
__global__ void k_loss(const float* __restrict__ pred, const float* __restrict__ target,
                       float* __restrict__ out) {
    __shared__ float sinv[16];
    __shared__ float swarp[16];
    __shared__ unsigned sred[8];
    __shared__ int s_flag;
    int b = blockIdx.x >> 6;                 // 64 blocks per batch (grid 1024, 512 thr)
    if (threadIdx.x < 16) sinv[threadIdx.x] = g_inv[b * GG + threadIdx.x];
    __syncthreads();
    unsigned p0 = blockIdx.x * 2048u + threadIdx.x * 4u;   // 4 consecutive points/thread
    unsigned mg = __ldg(&g_mg[p0 >> 2]);
    const float4* pp = reinterpret_cast<const float4*>(pred + 3u * p0);
    const float4* tt = reinterpret_cast<const float4*>(target + 3u * p0);
    float4 pa = pp[0], pb = pp[1], pc = pp[2];
    float4 ta = tt[0], tb = tt[1], tc = tt[2];
    float pr[12] = {pa.x, pa.y, pa.z, pa.w, pb.x, pb.y, pb.z, pb.w, pc.x, pc.y, pc.z, pc.w};
    float tr[12] = {ta.x, ta.y, ta.z, ta.w, tb.x, tb.y, tb.z, tb.w, tc.x, tc.y, tc.z, tc.w};
    float acc = 0.f;
#pragma unroll
    for (int e = 0; e < 4; e++) {
        unsigned byte = (mg >> (8 * e)) & 0xFFu;
        if (byte & 0x10u) {
            float inv = sinv[byte & 15u];
#pragma unroll
            for (int c = 0; c < 3; c++) {
                float p = pr[e * 3 + c] * inv;
                float t = tr[e * 3 + c] * inv;
                float u = fabsf(p); if (!(u <= 3.0e38f)) u = 0.f;   // nan_to_num
                float v = fabsf(t); if (!(v <= 3.0e38f)) v = 0.f;
                float la = __logf(1.f + u);
                float lb = __logf(1.f + v);
                bool same = (p >= 0.f) == (t >= 0.f);
                acc += fabsf(la - (same ? lb : -lb));
            }
        }
    }
#pragma unroll
    for (int o = 16; o; o >>= 1) acc += __shfl_down_sync(0xffffffffu, acc, o);
    if ((threadIdx.x & 31) == 0) swarp[threadIdx.x >> 5] = acc;
    __syncthreads();
    if (threadIdx.x == 0) {
        float s = 0.f;
#pragma unroll
        for (int w = 0; w < 16; w++) s += swarp[w];
        atomicAdd(&g_psum[blockIdx.x & 31], (double)s);
        __threadfence();
        unsigned d = atomicAdd(&g_done, 1u);
        s_flag = (d == gridDim.x - 1u);
    }
    __syncthreads();
    if (s_flag) {
        unsigned c = (threadIdx.x < 256) ? g_bcnt[threadIdx.x] : 0u;
#pragma unroll
        for (int o = 16; o; o >>= 1) c += __shfl_down_sync(0xffffffffu, c, o);
        if ((threadIdx.x & 31) == 0) sred[threadIdx.x >> 5] = c;
        __syncthreads();
        if (threadIdx.x == 0) {
            unsigned total = 0;
#pragma unroll
            for (int w = 0; w < 8; w++) total += sred[w];
            double ssum = 0.0;
#pragma unroll
            for (int j = 0; j < 32; j++) ssum += g_psum[j];
            out[0] = (float)(ssum / (3.0 * (double)total + 1e-6));
        }
        __syncthreads();
        // restore scratch to all-zero for the next (graph-replayed) launch
        if (threadIdx.x < 256) g_bcnt[threadIdx.x] = 0u;
        if (threadIdx.x < 32) g_psum[threadIdx.x] = 0.0;
        if (threadIdx.x == 0) g_done = 0u;
    }
}

extern "C" void kernel_launch(void* const* d_in, const int* in_sizes, int n_in,
                              void* d_out, int out_size) {
    const float* pred   = (const float*)d_in[0];
    const float* target = (const float*)d_in[1];
    const int*   mask   = (const int*)d_in[2];
    const int*   groups = (const int*)d_in[3];
    float* out = (float*)d_out;
    (void)in_sizes; (void)n_in; (void)out_size;

    k_scatter<<<1024, 256>>>(target, mask, groups);
    k_select <<<256,  512>>>();
    k_loss   <<<1024, 512>>>(pred, target, out);
}

// round 6
// speedup vs baseline: 1.0608x; 1.0608x over previous
#include <cuda_runtime.h>
#include <math.h>

#define BB 16
#define NN 131072
#define GG 16
#define BN (BB*NN)
#define BG (BB*GG)
#define CAP 16384            // per-(b,g) bucket capacity (expected ~4096, huge margin)

// ---------------- scratch (device globals; zero at load, re-zeroed by finalizer) ----------------
__device__ unsigned g_ckeys[BG * CAP];   // bucketed keys, segment bg at bg*CAP
__device__ unsigned g_bcnt[BG];          // per-(b,g) counts (start 0 each launch)
__device__ unsigned g_mg[BN / 4];        // packed (valid<<4)|group, one byte/point
__device__ float    g_inv[BG];           // 1 / clamp(|median|, eps)
__device__ double   g_psum[32];          // distributed loss partials
__device__ unsigned g_done;              // loss block completion counter

// order-preserving map f32 -> u32 (ascending)
__device__ __forceinline__ unsigned key_of(float z) {
    unsigned u = __float_as_uint(z);
    return (u & 0x80000000u) ? ~u : (u | 0x80000000u);
}

// ---------------- K1: bucketed scatter, 4 pts/thread, smem-staged coalesced writes ----------------
__global__ void k_scatter(const float* __restrict__ target, const int* __restrict__ mask,
                          const int* __restrict__ groups) {
    __shared__ unsigned s_cnt[32][16];     // slot = wid*4 + e
    __shared__ unsigned s_gstart[17];      // block-local group starts (+ total)
    __shared__ unsigned s_gbase[16];       // global base per group
    __shared__ unsigned s_keys[1024];      // staged keys grouped by bucket
    __shared__ unsigned char s_gid[1024];  // group id per staged key
    unsigned p0 = blockIdx.x * 1024u + threadIdx.x * 4u;  // 4 consecutive points/thread
    int b = blockIdx.x >> 7;               // 128 blocks per batch
    int wid = threadIdx.x >> 5, lane = threadIdx.x & 31;

    ((unsigned*)s_cnt)[threadIdx.x] = 0;
    ((unsigned*)s_cnt)[256 + threadIdx.x] = 0;

    int4 m4 = *reinterpret_cast<const int4*>(mask + p0);
    int4 g4 = *reinterpret_cast<const int4*>(groups + p0);
    const float4* tt = reinterpret_cast<const float4*>(target + 3u * p0);
    float4 t0 = tt[0], t1 = tt[1], t2 = tt[2];
    int   m[4] = {m4.x, m4.y, m4.z, m4.w};
    int   g[4] = {g4.x & 15, g4.y & 15, g4.z & 15, g4.w & 15};
    float z[4] = {t0.z, t1.y, t2.x, t2.w};

    unsigned mg = 0;
#pragma unroll
    for (int e = 0; e < 4; e++)
        mg |= ((m[e] ? 0x10u : 0u) | (unsigned)g[e]) << (8 * e);
    g_mg[p0 >> 2] = mg;
    __syncthreads();   // s_cnt zero visible

    unsigned peers[4];
#pragma unroll
    for (int e = 0; e < 4; e++) {
        unsigned tag = m[e] ? (unsigned)g[e] : 0xFFFFFFFFu;
        peers[e] = __match_any_sync(0xffffffffu, tag);
        if (m[e] && lane == (__ffs(peers[e]) - 1))
            s_cnt[wid * 4 + e][g[e]] = __popc(peers[e]);
    }
    __syncthreads();

    if (threadIdx.x < 16) {
        unsigned run = 0;
#pragma unroll
        for (int s = 0; s < 32; s++) {
            unsigned c = s_cnt[s][threadIdx.x];
            s_cnt[s][threadIdx.x] = run;
            run += c;
        }
        unsigned incl = run;
#pragma unroll
        for (int o = 1; o < 16; o <<= 1) {
            unsigned n = __shfl_up_sync(0x0000FFFFu, incl, o);
            if (lane >= o) incl += n;
        }
        s_gstart[threadIdx.x] = incl - run;
        if (threadIdx.x == 15) s_gstart[16] = incl;
        s_gbase[threadIdx.x] = run ? atomicAdd(&g_bcnt[b * GG + threadIdx.x], run) : 0u;
    }
    __syncthreads();

#pragma unroll
    for (int e = 0; e < 4; e++) {
        if (m[e]) {
            unsigned local = s_gstart[g[e]] + s_cnt[wid * 4 + e][g[e]]
                           + __popc(peers[e] & ((1u << lane) - 1u));
            s_keys[local] = key_of(z[e]);
            s_gid[local] = (unsigned char)g[e];
        }
    }
    __syncthreads();

    unsigned total = s_gstart[16];
    for (unsigned idx = threadIdx.x; idx < total; idx += 256u) {
        unsigned key = s_keys[idx];
        int gg = s_gid[idx];
        unsigned dst = (unsigned)(b * GG + gg) * CAP + s_gbase[gg] + (idx - s_gstart[gg]);
        g_ckeys[dst] = key;   // coalesced runs per group
    }
}

// ---------------- K2: per-(b,g) lower-median, smem-resident 8-bit radix select ----------------
#define SELCAP 12288
__global__ void k_select() {
    __shared__ unsigned s_hist[256];
    __shared__ unsigned s_wsum[8];
    __shared__ unsigned s_buf[SELCAP];
    __shared__ unsigned sh_sel, sh_k;
    int bg = blockIdx.x;
    unsigned segbase = (unsigned)bg * CAP;
    unsigned cnt = g_bcnt[bg];
    if (cnt == 0) {
        if (threadIdx.x == 0) g_inv[bg] = 1.0f;
        return;
    }
    bool in_smem = (cnt <= SELCAP);
    if (in_smem)
        for (unsigned i = threadIdx.x; i < cnt; i += 512u) s_buf[i] = g_ckeys[segbase + i];
    __syncthreads();

    unsigned k = (cnt - 1u) >> 1;            // lower median index
    unsigned prefix = 0, pmask = 0;
    int t = threadIdx.x, lane = t & 31;

    for (int level = 0; level < 4; level++) {
        int shift = 24 - 8 * level;
        if (t < 256) s_hist[t] = 0;
        __syncthreads();
        for (unsigned i = t; i < ((cnt + 511u) & ~511u); i += 512u) {
            unsigned bin = 0xFFFFFFFFu;
            if (i < cnt) {
                unsigned key = in_smem ? s_buf[i] : g_ckeys[segbase + i];
                if ((key & pmask) == prefix) bin = (key >> shift) & 255u;
            }
            unsigned peers = __match_any_sync(0xffffffffu, bin);
            if (bin != 0xFFFFFFFFu && lane == (__ffs(peers) - 1))
                atomicAdd(&s_hist[bin], (unsigned)__popc(peers));
        }
        __syncthreads();
        if (t < 256) {
            unsigned v = s_hist[t];
            unsigned incl = v;
#pragma unroll
            for (int o = 1; o < 32; o <<= 1) {
                unsigned n = __shfl_up_sync(0xffffffffu, incl, o);
                if (lane >= o) incl += n;
            }
            if (lane == 31) s_wsum[t >> 5] = incl;
        }
        __syncthreads();
        if (t < 256) {
            unsigned v = s_hist[t];
            unsigned incl = v;
#pragma unroll
            for (int o = 1; o < 32; o <<= 1) {
                unsigned n = __shfl_up_sync(0xffffffffu, incl, o);
                if (lane >= o) incl += n;
            }
            unsigned off = 0;
#pragma unroll
            for (int w = 0; w < 8; w++) off += (w < (t >> 5)) ? s_wsum[w] : 0u;
            incl += off;
            unsigned excl = incl - v;
            if (k >= excl && k < incl) { sh_sel = (unsigned)t; sh_k = k - excl; }
        }
        __syncthreads();
        prefix |= sh_sel << shift;
        pmask  |= 255u << shift;
        k = sh_k;
        __syncthreads();
    }
    if (t == 0) {
        unsigned kk = prefix;
        unsigned ub = (kk & 0x80000000u) ? (kk & 0x7fffffffu) : ~kk;
        float med = __uint_as_float(ub);
        if (!isfinite(med)) med = 1.0f;      // nan_to_num semantics
        float ns = fmaxf(fabsf(med), 1e-6f);
        g_inv[bg] = 1.0f / ns;
    }
}

// ---------------- K3: fused loss pass + reduction + last-block finalize/reset ----------------
__global__ void k_loss(const float* __restrict__ pred, const float* __restrict__ target,
                       float* __restrict__ out) {
    __shared__ float sinv[16];
    __shared__ float swarp[8];
    __shared__ unsigned sred[8];
    __shared__ int s_flag;
    int b = blockIdx.x >> 7;
    if (threadIdx.x < 16) sinv[threadIdx.x] = g_inv[b * GG + threadIdx.x];
    __syncthreads();
    unsigned p0 = blockIdx.x * 1024u + threadIdx.x * 4u;   // 4 consecutive points/thread
    unsigned mg = __ldg(&g_mg[p0 >> 2]);
    const float4* pp = reinterpret_cast<const float4*>(pred + 3u * p0);
    const float4* tt = reinterpret_cast<const float4*>(target + 3u * p0);
    float4 pa = pp[0], pb = pp[1], pc = pp[2];
    float4 ta = tt[0], tb = tt[1], tc = tt[2];
    float pr[12] = {pa.x, pa.y, pa.z, pa.w, pb.x, pb.y, pb.z, pb.w, pc.x, pc.y, pc.z, pc.w};
    float tr[12] = {ta.x, ta.y, ta.z, ta.w, tb.x, tb.y, tb.z, tb.w, tc.x, tc.y, tc.z, tc.w};
    float acc = 0.f;
#pragma unroll
    for (int e = 0; e < 4; e++) {
        unsigned byte = (mg >> (8 * e)) & 0xFFu;
        if (byte & 0x10u) {
            float inv = sinv[byte & 15u];
#pragma unroll
            for (int c = 0; c < 3; c++) {
                float p = pr[e * 3 + c] * inv;
                float t = tr[e * 3 + c] * inv;
                float u = fabsf(p); if (!(u <= 3.0e38f)) u = 0.f;   // nan_to_num
                float v = fabsf(t); if (!(v <= 3.0e38f)) v = 0.f;
                // |s_p*log1p(u) - s_t*log1p(v)| fused into a single log:
                //   same sign: |log((1+u)/(1+v))|     diff sign: log((1+u)(1+v))
                float a = 1.f + u, q = 1.f + v;
                bool same = (p >= 0.f) == (t >= 0.f);
                float r = same ? __fdividef(a, q) : a * q;
                acc += fabsf(__logf(r));
            }
        }
    }
#pragma unroll
    for (int o = 16; o; o >>= 1) acc += __shfl_down_sync(0xffffffffu, acc, o);
    if ((threadIdx.x & 31) == 0) swarp[threadIdx.x >> 5] = acc;
    __syncthreads();
    if (threadIdx.x == 0) {
        float s = 0.f;
#pragma unroll
        for (int w = 0; w < 8; w++) s += swarp[w];
        atomicAdd(&g_psum[blockIdx.x & 31], (double)s);
        __threadfence();
        unsigned d = atomicAdd(&g_done, 1u);
        s_flag = (d == gridDim.x - 1u);
    }
    __syncthreads();
    if (s_flag) {
        unsigned c = g_bcnt[threadIdx.x];       // 256 threads, 256 counters
#pragma unroll
        for (int o = 16; o; o >>= 1) c += __shfl_down_sync(0xffffffffu, c, o);
        if ((threadIdx.x & 31) == 0) sred[threadIdx.x >> 5] = c;
        __syncthreads();
        if (threadIdx.x == 0) {
            unsigned total = 0;
#pragma unroll
            for (int w = 0; w < 8; w++) total += sred[w];
            double ssum = 0.0;
#pragma unroll
            for (int j = 0; j < 32; j++) ssum += g_psum[j];
            out[0] = (float)(ssum / (3.0 * (double)total + 1e-6));
        }
        __syncthreads();
        // restore scratch to all-zero for the next (graph-replayed) launch
        g_bcnt[threadIdx.x] = 0u;
        if (threadIdx.x < 32) g_psum[threadIdx.x] = 0.0;
        if (threadIdx.x == 0) g_done = 0u;
    }
}

extern "C" void kernel_launch(void* const* d_in, const int* in_sizes, int n_in,
                              void* d_out, int out_size) {
    const float* pred   = (const float*)d_in[0];
    const float* target = (const float*)d_in[1];
    const int*   mask   = (const int*)d_in[2];
    const int*   groups = (const int*)d_in[3];
    float* out = (float*)d_out;
    (void)in_sizes; (void)n_in; (void)out_size;

    k_scatter<<<2048, 256>>>(target, mask, groups);
    k_select <<<256,  512>>>();
    k_loss   <<<2048, 256>>>(pred, target, out);
}